// round 6
// baseline (speedup 1.0000x reference)
#include <cuda_runtime.h>

#define NN 50000
#define NE 600000
#define DD 128
#define SCAN_B 1024
#define SCAN_G ((NN + SCAN_B - 1) / SCAN_B)   // 49

// ---------------- scratch (static device globals; no allocation) ----------------
__device__ float  g_xw[NN * DD];                // x @ W fp32, 25.6 MB (L2-resident)
__device__ int    g_degi[NN];                   // zeroed at load; fill re-zeroes after use
__device__ int    g_start[NN];
__device__ int    g_cur[NN];
__device__ unsigned int g_adj[NE];              // src index per edge (CSR by dst)
__device__ float  g_dinv[NN];
__device__ int    g_bsum[SCAN_G];
__device__ float  g_sum[DD];                    // zeroed at load; scan1 re-zeroes each run
__device__ float  g_sumsq[DD];

// ---- local int64/int32 detection: values < 50000 => int64 odd words are all 0 ---
__device__ __forceinline__ int detect_is64(const unsigned int* __restrict__ e) {
    int is64 = 1;
    #pragma unroll
    for (int i = 0; i < 16; i++)
        if (e[2 * i + 1] != 0u) { is64 = 0; break; }
    return is64;
}

// ---------------- degree over dst ----------------
__global__ void deg_kernel(const unsigned int* __restrict__ e) {
    __shared__ int s64;
    if (threadIdx.x == 0) s64 = detect_is64(e);
    __syncthreads();
    int t = blockIdx.x * blockDim.x + threadIdx.x;
    if (t >= NE) return;
    int d;
    if (s64) d = (int)((const long long*)e)[NE + t];
    else     d = ((const int*)e)[NE + t];
    atomicAdd(&g_degi[d], 1);
}

// -------- scan phase 1: per-block totals + dinv; block 0 re-zeroes BN stats ------
__global__ void __launch_bounds__(SCAN_B) scan1_kernel() {
    __shared__ int wsums[32];
    const int tid = threadIdx.x, lane = tid & 31, wid = tid >> 5;
    if (blockIdx.x == 0 && tid < DD) { g_sum[tid] = 0.0f; g_sumsq[tid] = 0.0f; }
    const int i = blockIdx.x * SCAN_B + tid;
    int d = (i < NN) ? g_degi[i] : 0;
    if (i < NN) g_dinv[i] = rsqrtf((float)d + 1.0f);   // +1 = self loop

    int v = d;
    #pragma unroll
    for (int o = 16; o > 0; o >>= 1) v += __shfl_down_sync(0xffffffffu, v, o);
    if (lane == 0) wsums[wid] = v;
    __syncthreads();
    if (wid == 0) {
        int wv = wsums[lane];
        #pragma unroll
        for (int o = 16; o > 0; o >>= 1) wv += __shfl_down_sync(0xffffffffu, wv, o);
        if (lane == 0) g_bsum[blockIdx.x] = wv;
    }
}

// -------- scan phase 3 (scan2 inlined): block offset + local scan -> start/cur ---
__global__ void __launch_bounds__(SCAN_B) scan3_kernel() {
    __shared__ int wsums[32];
    __shared__ int bpart[2];
    const int tid = threadIdx.x, lane = tid & 31, wid = tid >> 5;

    if (tid < 64) {
        int t = (tid < (int)blockIdx.x) ? g_bsum[tid] : 0;
        #pragma unroll
        for (int o = 16; o > 0; o >>= 1) t += __shfl_down_sync(0xffffffffu, t, o);
        if (lane == 0) bpart[tid >> 5] = t;
    }

    const int i = blockIdx.x * SCAN_B + tid;
    int d = (i < NN) ? g_degi[i] : 0;
    int v = d;
    #pragma unroll
    for (int o = 1; o < 32; o <<= 1) {
        int t = __shfl_up_sync(0xffffffffu, v, o);
        if (lane >= o) v += t;
    }
    if (lane == 31) wsums[wid] = v;
    __syncthreads();
    if (wid == 0) {
        int wv = wsums[lane];
        #pragma unroll
        for (int o = 1; o < 32; o <<= 1) {
            int t = __shfl_up_sync(0xffffffffu, wv, o);
            if (lane >= o) wv += t;
        }
        wsums[lane] = wv;
    }
    __syncthreads();
    if (i < NN) {
        int boff = bpart[0] + bpart[1];
        int excl = boff + (wid > 0 ? wsums[wid - 1] : 0) + (v - d);
        g_start[i] = excl;
        g_cur[i]   = excl;
    }
}

// -------- adjacency fill: src per edge; also re-zero g_degi for next replay ------
__global__ void fill_kernel(const unsigned int* __restrict__ e) {
    __shared__ int s64;
    if (threadIdx.x == 0) s64 = detect_is64(e);
    __syncthreads();
    int t = blockIdx.x * blockDim.x + threadIdx.x;
    if (t >= NE) return;
    if (t < NN) g_degi[t] = 0;     // last reader (scan3) already ran
    int s, d;
    if (s64) {
        s = (int)((const long long*)e)[t];
        d = (int)((const long long*)e)[NE + t];
    } else {
        s = ((const int*)e)[t];
        d = ((const int*)e)[NE + t];
    }
    int p = atomicAdd(&g_cur[d], 1);
    g_adj[p] = (unsigned int)s;
}

// ---------------- GEMM: g_xw = x @ W (fp32), packed fma.rn.f32x2 -----------------
__global__ void __launch_bounds__(128) gemm_kernel(const float* __restrict__ x,
                                                   const float* __restrict__ W) {
    __shared__ unsigned long long xs[32][DD];   // 32 KB
    const int tid = threadIdx.x;
    const int r0  = blockIdx.x * 32;

    for (int idx = tid; idx < 32 * DD; idx += 128) {
        int row = idx >> 7, k = idx & 127;
        float v = (r0 + row < NN) ? x[(size_t)(r0 + row) * DD + k] : 0.0f;
        unsigned int u = __float_as_uint(v);
        xs[row][k] = ((unsigned long long)u << 32) | u;
    }
    __syncthreads();

    const int cg = tid & 31;
    const int rg = tid >> 5;
    unsigned long long a[8][2];
    #pragma unroll
    for (int r = 0; r < 8; r++) { a[r][0] = 0ull; a[r][1] = 0ull; }

    const float4* __restrict__ W4 = (const float4*)W;
    #pragma unroll 4
    for (int k = 0; k < DD; k++) {
        float4 w = W4[k * 32 + cg];
        unsigned long long wxy, wzw;
        asm("mov.b64 %0, {%1,%2};" : "=l"(wxy) : "f"(w.x), "f"(w.y));
        asm("mov.b64 %0, {%1,%2};" : "=l"(wzw) : "f"(w.z), "f"(w.w));
        #pragma unroll
        for (int r = 0; r < 8; r++) {
            unsigned long long xd = xs[rg * 8 + r][k];
            asm("fma.rn.f32x2 %0, %1, %2, %0;" : "+l"(a[r][0]) : "l"(xd), "l"(wxy));
            asm("fma.rn.f32x2 %0, %1, %2, %0;" : "+l"(a[r][1]) : "l"(xd), "l"(wzw));
        }
    }

    float4* __restrict__ out4 = (float4*)g_xw;
    #pragma unroll
    for (int r = 0; r < 8; r++) {
        int row = r0 + rg * 8 + r;
        if (row < NN) {
            float4 o;
            asm("mov.b64 {%0,%1}, %2;" : "=f"(o.x), "=f"(o.y) : "l"(a[r][0]));
            asm("mov.b64 {%0,%1}, %2;" : "=f"(o.z), "=f"(o.w) : "l"(a[r][1]));
            out4[(size_t)row * 32 + cg] = o;
        }
    }
}

// ---- gather: warp per node, fp32, batched adj+dinv, norm folded as dinv[s] ------
__global__ void __launch_bounds__(256) gather_kernel(const float* __restrict__ bias,
                                                     float* __restrict__ z) {
    const int tid   = threadIdx.x;
    const int lane  = tid & 31;
    const int wid   = tid >> 5;
    const int warpg = (blockIdx.x * 256 + tid) >> 5;
    const int nwarp = gridDim.x * 8;

    const float4* __restrict__ xw4   = (const float4*)g_xw;
    const float4* __restrict__ bias4 = (const float4*)bias;
    float4*       __restrict__ z4    = (float4*)z;

    const float4 b = bias4[lane];
    float4 ls = make_float4(0.f, 0.f, 0.f, 0.f);
    float4 lq = ls;

    for (int node = warpg; node < NN; node += nwarp) {
        const int beg = g_start[node];
        const int end = g_cur[node];
        const float di = g_dinv[node];

        // self loop: xw[node]*di (final *di below makes it di^2)
        float4 acc = __ldcg(&xw4[(size_t)node * 32 + lane]);
        acc.x *= di; acc.y *= di; acc.z *= di; acc.w *= di;

        for (int base = beg; base < end; base += 32) {
            const int cnt = min(32, end - base);
            unsigned int sv = (lane < cnt) ? g_adj[base + lane] : 0u;  // coalesced
            float dv = __ldg(&g_dinv[sv]);                              // small L1-hot table
            #pragma unroll 4
            for (int j = 0; j < cnt; j++) {
                unsigned int s = __shfl_sync(0xffffffffu, sv, j);
                float        n = __shfl_sync(0xffffffffu, dv, j);
                float4 v = __ldcg(&xw4[(size_t)s * 32 + lane]);
                acc.x += v.x * n; acc.y += v.y * n;
                acc.z += v.z * n; acc.w += v.w * n;
            }
        }

        float4 v;
        v.x = fmaxf(acc.x * di + b.x, 0.0f);
        v.y = fmaxf(acc.y * di + b.y, 0.0f);
        v.z = fmaxf(acc.z * di + b.z, 0.0f);
        v.w = fmaxf(acc.w * di + b.w, 0.0f);
        z4[(size_t)node * 32 + lane] = v;

        ls.x += v.x; ls.y += v.y; ls.z += v.z; ls.w += v.w;
        lq.x += v.x * v.x; lq.y += v.y * v.y; lq.z += v.z * v.z; lq.w += v.w * v.w;
    }

    __shared__ float rs[8][DD];
    __shared__ float rq[8][DD];
    ((float4*)&rs[wid][0])[lane] = ls;
    ((float4*)&rq[wid][0])[lane] = lq;
    __syncthreads();
    if (tid < DD) {
        float s = 0.f, q = 0.f;
        #pragma unroll
        for (int w = 0; w < 8; w++) { s += rs[w][tid]; q += rq[w][tid]; }
        atomicAdd(&g_sum[tid], s);
        atomicAdd(&g_sumsq[tid], q);
    }
}

// --------- fused BN params + normalize + dropout (params recomputed/block) -------
__global__ void __launch_bounds__(256) final_kernel(const float* __restrict__ gamma,
                                                    const float* __restrict__ beta,
                                                    const float* __restrict__ u,
                                                    float* __restrict__ z) {
    __shared__ float sc[DD], sh[DD];
    const int tid = threadIdx.x;
    if (tid < DD) {
        float mean = g_sum[tid] * (1.0f / NN);
        float var  = g_sumsq[tid] * (1.0f / NN) - mean * mean;
        float s    = gamma[tid] * rsqrtf(var + 1e-5f);
        sc[tid] = s;
        sh[tid] = beta[tid] - mean * s;
    }
    __syncthreads();

    int gid = blockIdx.x * blockDim.x + tid;
    if (gid >= NN * 32) return;
    int j4 = (gid & 31) * 4;

    float4 v  = ((const float4*)z)[gid];
    float4 uu = ((const float4*)u)[gid];
    const float inv_keep = 1.0f / 0.9f;

    float4 r;
    r.x = (uu.x > 0.1f) ? (v.x * sc[j4 + 0] + sh[j4 + 0]) * inv_keep : 0.0f;
    r.y = (uu.y > 0.1f) ? (v.y * sc[j4 + 1] + sh[j4 + 1]) * inv_keep : 0.0f;
    r.z = (uu.z > 0.1f) ? (v.z * sc[j4 + 2] + sh[j4 + 2]) * inv_keep : 0.0f;
    r.w = (uu.w > 0.1f) ? (v.w * sc[j4 + 3] + sh[j4 + 3]) * inv_keep : 0.0f;
    ((float4*)z)[gid] = r;
}

// ---------------- launch: 7 graph nodes, GEMM forked onto side stream ------------
extern "C" void kernel_launch(void* const* d_in, const int* in_sizes, int n_in,
                              void* d_out, int out_size) {
    const float* x      = (const float*)d_in[0];
    const float* weight = (const float*)d_in[1];
    const float* bias   = (const float*)d_in[2];
    const float* gamma  = (const float*)d_in[3];
    const float* beta   = (const float*)d_in[4];
    const float* drop_u = (const float*)d_in[5];
    const unsigned int* eidx = (const unsigned int*)d_in[6];

    float* z = (float*)d_out;

    static cudaStream_t s2 = nullptr;
    static cudaEvent_t evf = nullptr, evj = nullptr;
    if (s2 == nullptr) {
        cudaStreamCreateWithFlags(&s2, cudaStreamNonBlocking);
        cudaEventCreateWithFlags(&evf, cudaEventDisableTiming);
        cudaEventCreateWithFlags(&evj, cudaEventDisableTiming);
    }

    // fork GEMM (depends only on inputs)
    cudaEventRecord(evf, 0);
    cudaStreamWaitEvent(s2, evf, 0);
    gemm_kernel<<<(NN + 31) / 32, 128, 0, s2>>>(x, weight);
    cudaEventRecord(evj, s2);

    // main chain: edge preprocessing
    deg_kernel<<<(NE + 255) / 256, 256>>>(eidx);
    scan1_kernel<<<SCAN_G, SCAN_B>>>();
    scan3_kernel<<<SCAN_G, SCAN_B>>>();
    fill_kernel<<<(NE + 255) / 256, 256>>>(eidx);

    // join: gather needs CSR + GEMM output
    cudaStreamWaitEvent(0, evj, 0);
    gather_kernel<<<592, 256>>>(bias, z);
    final_kernel<<<(NN * 32 + 255) / 256, 256>>>(gamma, beta, drop_u, z);
}